// round 11
// baseline (speedup 1.0000x reference)
#include <cuda_runtime.h>
#include <math.h>

#define K_TOP    6000
#define CAND_CAP 16384
#define BIN_CAP  16384
#define NMS_CAP  1024
#define HBINS    4096      // 12-bit histogram (top 12 bits of transformed score)
#define H2BINS   4096      // 12-bit refine histogram (bits [8,20))
#define MSTRIDE  33        // padded mask row stride (no 32-way bank conflicts)
#define NGROUPS  16

// ---------------- scratch (device globals; no allocations) ----------------
__device__ unsigned int       g_hist[HBINS];
__device__ unsigned int       g_hist2[H2BINS];
__device__ unsigned int       g_base[HBINS];    // per-bin global rank base (suffix sum)
__device__ unsigned int       g_cursor[HBINS];  // per-bin scatter cursor
__device__ unsigned int       g_meta[8];        // [0]=t12 [1]=s_cnt [4]=bin counter
__device__ unsigned long long g_cand[CAND_CAP]; // definite candidates, bucketed by bin
__device__ unsigned long long g_bin[BIN_CAP];   // crossing-bin keys (unordered)
__device__ float4             g_gbox[NGROUPS * NMS_CAP];
__device__ int                g_gpos[NGROUPS * NMS_CAP];
__device__ unsigned int       g_gcnt[NGROUPS];

// order-preserving float<->uint transform
__device__ __forceinline__ unsigned int f2u(float f) {
    unsigned int b = __float_as_uint(f);
    return b ^ ((b & 0x80000000u) ? 0xFFFFFFFFu : 0x80000000u);
}
__device__ __forceinline__ float u2f(unsigned int u) {
    unsigned int b = (u & 0x80000000u) ? (u ^ 0x80000000u) : ~u;
    return __uint_as_float(b);
}

// warp-ballot-aggregated append of `key` when `e` is true (shared counter)
__device__ __forceinline__ void ballot_append(bool e, unsigned long long key,
                                              unsigned long long* buf,
                                              unsigned int* ctr,
                                              int lane, unsigned int cap) {
    unsigned int act = __activemask();
    unsigned int ball = __ballot_sync(act, e);
    if (!ball) return;
    int leader = __ffs(ball) - 1;
    unsigned int posb = 0;
    if (lane == leader) posb = atomicAdd(ctr, (unsigned int)__popc(ball));
    posb = __shfl_sync(act, posb, leader);
    if (e) {
        unsigned int my = posb + __popc(ball & ((1u << lane) - 1u));
        if (my < cap) buf[my] = key;
    }
}

// block-wide suffix-sum threshold find over histogram H[BINS]
template<int BINS, int NT>
__device__ __forceinline__ void find_threshold(const unsigned int* H,
                                               unsigned int need,
                                               unsigned int* ssum,
                                               volatile unsigned int* o_t,
                                               volatile unsigned int* o_cnt) {
    int tid = threadIdx.x;
    const int bpt = BINS / NT;
    unsigned int cs = 0;
    int base = tid * bpt;
#pragma unroll
    for (int k = 0; k < bpt; k++) cs += H[base + k];
    ssum[tid] = cs; __syncthreads();
    for (int off = 1; off < NT; off <<= 1) {           // inclusive suffix sum
        unsigned int v = (tid + off < NT) ? ssum[tid + off] : 0u;
        __syncthreads();
        ssum[tid] += v;
        __syncthreads();
    }
    unsigned int excl = (tid < NT - 1) ? ssum[tid + 1] : 0u;
    if (ssum[tid] >= need && excl < need) {            // unique crossing chunk
        unsigned int run = excl;
        for (int k = bpt - 1; k >= 0; k--) {
            unsigned int h = H[base + k];
            if (run + h >= need) { *o_t = (unsigned int)(base + k); *o_cnt = run; break; }
            run += h;
        }
    }
    __syncthreads();
}

// ---------------- kernel 1: 12-bit histogram of fg scores ----------------
__global__ void k_hist(const float* __restrict__ probs, int n_groups) {
    __shared__ unsigned int sh[HBINS];
    for (int k = threadIdx.x; k < HBINS; k += blockDim.x) sh[k] = 0u;
    __syncthreads();

    const float4* __restrict__ p4 = (const float4*)probs;
    int stride = gridDim.x * blockDim.x;
    for (int g = blockIdx.x * blockDim.x + threadIdx.x; g < n_groups; g += stride) {
        float4 A = p4[g * 3 + 0], B = p4[g * 3 + 1], C = p4[g * 3 + 2];
        float s[8] = {A.y, A.z, B.x, B.y, B.w, C.x, C.z, C.w};
#pragma unroll
        for (int k = 0; k < 8; k++) {
            unsigned int bin = f2u(s[k]) >> 20;
            unsigned int act = __activemask();
            unsigned int peers = __match_any_sync(act, bin);
            int leader = __ffs(peers) - 1;
            if ((threadIdx.x & 31) == leader)
                atomicAdd(&sh[bin], (unsigned int)__popc(peers));
        }
    }
    __syncthreads();
    for (int k = threadIdx.x; k < HBINS; k += blockDim.x) {
        unsigned int v = sh[k];
        if (v) atomicAdd(&g_hist[k], v);
    }
}

// --- kernel 2: crossing bin + per-bin rank bases (suffix sums) + cursors ---
__global__ void k_binit() {
    __shared__ unsigned int ssum[1024];
    int tid = threadIdx.x;
    const int bpt = HBINS / 1024;    // 4
    int base = tid * bpt;
    unsigned int cs = 0;
#pragma unroll
    for (int k = 0; k < bpt; k++) cs += g_hist[base + k];
    ssum[tid] = cs; __syncthreads();
    for (int off = 1; off < 1024; off <<= 1) {
        unsigned int v = (tid + off < 1024) ? ssum[tid + off] : 0u;
        __syncthreads();
        ssum[tid] += v;
        __syncthreads();
    }
    unsigned int excl = (tid < 1023) ? ssum[tid + 1] : 0u;

    unsigned int run = excl;                 // suffix base per bin
#pragma unroll
    for (int k = bpt - 1; k >= 0; k--) {
        g_base[base + k] = run;
        g_cursor[base + k] = run;
        run += g_hist[base + k];
    }
    if (ssum[tid] >= (unsigned)K_TOP && excl < (unsigned)K_TOP) {
        unsigned int r2 = excl;
        for (int k = bpt - 1; k >= 0; k--) {
            unsigned int h = g_hist[base + k];
            if (r2 + h >= (unsigned)K_TOP) {
                g_meta[0] = (unsigned int)(base + k);   // t12
                g_meta[1] = r2;                         // s_cnt (strictly above)
                break;
            }
            r2 += h;
        }
    }
}

// --- kernel 3: pass 2 -- definite candidates scattered into bin buckets,
//     crossing-bin keys stashed + refine histogram ---
__global__ void k_hist2s(const float* __restrict__ probs, int n_groups) {
    __shared__ unsigned int sh[H2BINS];
    unsigned int t = g_meta[0];
    for (int k = threadIdx.x; k < H2BINS; k += blockDim.x) sh[k] = 0u;
    __syncthreads();

    int lane = threadIdx.x & 31;
    const float4* __restrict__ p4 = (const float4*)probs;
    int stride = gridDim.x * blockDim.x;
    for (int g = blockIdx.x * blockDim.x + threadIdx.x; g < n_groups; g += stride) {
        float4 A = p4[g * 3 + 0], B = p4[g * 3 + 1], C = p4[g * 3 + 2];
        float s[8] = {A.y, A.z, B.x, B.y, B.w, C.x, C.z, C.w};
#pragma unroll
        for (int k = 0; k < 8; k++) {
            unsigned int u = f2u(s[k]);
            unsigned int hi = u >> 20;
            unsigned int flat = (unsigned int)((g * 4 + (k >> 1)) * 2 + (k & 1));
            unsigned long long key = ((unsigned long long)u << 32) |
                                     (unsigned long long)(0xFFFFFFFFu - flat);
            bool e = (hi > t);
            unsigned int act = __activemask();
            unsigned int ball_e = __ballot_sync(act, e);
            if (ball_e) {
                unsigned int peers = __match_any_sync(act, hi) & ball_e;
                if (e) {
                    int leader = __ffs(peers) - 1;
                    unsigned int basep = 0;
                    if (lane == leader)
                        basep = atomicAdd(&g_cursor[hi], (unsigned int)__popc(peers));
                    basep = __shfl_sync(ball_e, basep, leader);
                    unsigned int my = basep + __popc(peers & ((1u << lane) - 1u));
                    if (my < CAND_CAP) g_cand[my] = key;
                }
            }
            bool inbin = (hi == t);
            ballot_append(inbin, key, g_bin, &g_meta[4], lane, BIN_CAP);
            if (inbin) atomicAdd(&sh[(u >> 8) & 0xFFFu], 1u);
        }
    }
    __syncthreads();
    for (int k = threadIdx.x; k < H2BINS; k += blockDim.x) {
        unsigned int v = sh[k];
        if (v) atomicAdd(&g_hist2[k], v);
    }
}

// --- kernel 4: bucketed exact rank + decode + group scatter ---
// definite: rank = g_base[bin] + greater-in-own-segment (segment tiny)
// crossing (passes t2): rank = s_cnt + greater-in-g_bin
__global__ void k_rank(const float* __restrict__ deltas,
                       const float* __restrict__ anchors,
                       float* __restrict__ out, int n_anchors) {
    __shared__ unsigned int ssum[512];
    __shared__ unsigned int s_t2, s_dum;
    int tid = threadIdx.x;
    int lane = tid & 31;

    unsigned int s_cnt = g_meta[1];
    find_threshold<H2BINS, 512>(g_hist2, (unsigned)K_TOP - s_cnt, ssum, &s_t2, &s_dum);
    unsigned int t2 = s_t2;

    int nb = (int)min(g_meta[4], (unsigned int)BIN_CAP);
    int total_items = (int)s_cnt + nb;
    int warp = blockIdx.x * (blockDim.x >> 5) + (tid >> 5);
    int nwarps = gridDim.x * (blockDim.x >> 5);

    for (int item = warp; item < total_items; item += nwarps) {
        unsigned long long key;
        int seg0, segn, rbase;
        if (item < (int)s_cnt) {
            key = g_cand[item];
            unsigned int bin = (unsigned int)(key >> 52);    // u >> 20
            seg0 = (int)g_base[bin];
            segn = (int)g_hist[bin];
            rbase = seg0;
        } else {
            key = g_bin[item - (int)s_cnt];
            unsigned int u = (unsigned int)(key >> 32);
            if (((u >> 8) & 0xFFFu) < t2) continue;   // provably rank >= K_TOP
            seg0 = 0; segn = nb; rbase = (int)s_cnt;
        }

        unsigned int cnt = 0u;
        const unsigned long long* buf = (item < (int)s_cnt) ? g_cand : g_bin;
        for (int j = seg0 + lane; j < seg0 + segn; j += 32)
            cnt += (buf[j] > key) ? 1u : 0u;
#pragma unroll
        for (int off = 16; off > 0; off >>= 1)
            cnt += __shfl_down_sync(0xFFFFFFFFu, cnt, off);

        if (lane == 0) {
            int rk = rbase + (int)cnt;
            if (rk < K_TOP) {
                unsigned int u = (unsigned int)(key >> 32);
                unsigned int flat = 0xFFFFFFFFu - (unsigned int)(key & 0xFFFFFFFFu);
                int prop = (int)(flat >> 1);
                int cls = (int)(flat & 1u) + 1;
                float score = u2f(u);
                int b = prop / n_anchors;
                int ai = prop - b * n_anchors;

                const float* a  = anchors + (size_t)ai * 4;
                const float* dl = deltas + (size_t)prop * 4;
                float d0 = dl[0] * 0.1f, d1 = dl[1] * 0.1f;
                float d2 = dl[2] * 0.2f, d3 = dl[3] * 0.2f;

                const float inv = 1.0f / 512.0f;
                float ay1 = a[0] * inv, ax1 = a[1] * inv;
                float ay2 = a[2] * inv, ax2 = a[3] * inv;
                float h  = ay2 - ay1;
                float w2 = ax2 - ax1;
                float cy = ay1 + 0.5f * h + d0 * h;
                float cx = ax1 + 0.5f * w2 + d1 * w2;
                h  = h * expf(d2);
                w2 = w2 * expf(d3);
                float y1 = cy - 0.5f * h;
                float x1 = cx - 0.5f * w2;
                float y2 = y1 + h;
                float x2 = x1 + w2;
                y1 = fminf(fmaxf(y1 * 512.0f, 0.0f), 512.0f);
                x1 = fminf(fmaxf(x1 * 512.0f, 0.0f), 512.0f);
                y2 = fminf(fmaxf(y2 * 512.0f, 0.0f), 512.0f);
                x2 = fminf(fmaxf(x2 * 512.0f, 0.0f), 512.0f);

                out[rk * 6 + 0] = y1;
                out[rk * 6 + 1] = x1;
                out[rk * 6 + 2] = y2;
                out[rk * 6 + 3] = x2;
                out[rk * 6 + 4] = score;
                out[rk * 6 + 5] = 1.0f;                 // keep (finalized by NMS)
                out[K_TOP * 6 + rk] = (float)cls;       // class_ids
                out[K_TOP * 7 + rk] = (float)b;         // batch ids

                int grp = b * 2 + (int)(flat & 1u);
                unsigned int slot = atomicAdd(&g_gcnt[grp], 1u);   // arbitrary order
                if (slot < NMS_CAP) {
                    g_gbox[grp * NMS_CAP + slot] = make_float4(y1, x1, y2, x2);
                    g_gpos[grp * NMS_CAP + slot] = rk;
                }
            }
        }
    }
}

// ------- kernel 5: per-group NMS (sorts by global rank first) + cleanup -------
__global__ void k_nms(float* __restrict__ out) {
    extern __shared__ unsigned char dyn[];
    float* sy1   = (float*)dyn;
    float* sx1   = sy1 + NMS_CAP;
    float* sy2   = sx1 + NMS_CAP;
    float* sx2   = sy2 + NMS_CAP;
    float* sarea = sx2 + NMS_CAP;
    int* spos    = (int*)(sarea + NMS_CAP);
    unsigned int* mask = (unsigned int*)(spos + NMS_CAP);   // [NMS_CAP][MSTRIDE]
    int* rkraw = (int*)mask;                                // pre-mask scratch

    __shared__ unsigned int s_remv[32];

    int tid = threadIdx.x;
    int grp = blockIdx.x;

    // cleanup scratch for next graph replay (g_base/g_cursor rewritten by k_binit)
    if (tid < HBINS / NGROUPS) g_hist[grp * (HBINS / NGROUPS) + tid] = 0u;
    else if (tid >= 256 && tid < 256 + H2BINS / NGROUPS)
        g_hist2[grp * (H2BINS / NGROUPS) + (tid - 256)] = 0u;
    if (grp == 0 && tid == 512) g_meta[4] = 0u;

    int n = min((int)g_gcnt[grp], NMS_CAP);

    // load raw (unordered) entries; sort by global rank via rank-by-count
    float4 bx = make_float4(0.f, 0.f, 0.f, 0.f);
    int ps = 0;
    if (tid < n) {
        bx = g_gbox[grp * NMS_CAP + tid];
        ps = g_gpos[grp * NMS_CAP + tid];
        rkraw[tid] = ps;
    }
    __syncthreads();
    if (tid == 0) g_gcnt[grp] = 0u;
    int myrank = 0;
    if (tid < n)
        for (int j = 0; j < n; j++) myrank += (rkraw[j] < ps) ? 1 : 0;
    __syncthreads();
    if (tid < n) {
        sy1[myrank] = bx.x; sx1[myrank] = bx.y;
        sy2[myrank] = bx.z; sx2[myrank] = bx.w;
        sarea[myrank] = (bx.z - bx.x + 1.0f) * (bx.w - bx.y + 1.0f);
        spos[myrank] = ps;
    }
    __syncthreads();

    int nw = (n + 31) >> 5;

    // forward suppression masks; t = w*n + i (i fastest): lanes share w,
    // consecutive i -> conflict-free mask stores with MSTRIDE=33
    int total = nw * n;
    for (int t = tid; t < total; t += blockDim.x) {
        int w = t / n;
        int i = t - w * n;
        if (w < (i >> 5)) { mask[i * MSTRIDE + w] = 0u; continue; }
        float iy1 = sy1[i], ix1 = sx1[i], iy2 = sy2[i], ix2 = sx2[i];
        float ia = sarea[i];
        unsigned int mw = 0u;
        int jb = w << 5;
#pragma unroll 8
        for (int b = 0; b < 32; b++) {
            int j = jb + b;
            if (j > i && j < n) {
                float ih  = fminf(iy2, sy2[j]) - fmaxf(iy1, sy1[j]) + 1.0f;
                float iw2 = fminf(ix2, sx2[j]) - fmaxf(ix1, sx1[j]) + 1.0f;
                ih = fmaxf(ih, 0.0f); iw2 = fmaxf(iw2, 0.0f);
                float inter = ih * iw2;
                if (inter >= 0.5f * (ia + sarea[j] - inter)) mw |= (1u << b);
            }
        }
        mask[i * MSTRIDE + w] = mw;
    }
    __syncthreads();

    // greedy bit-reduce (warp 0), visiting only still-alive boxes via ffs
    if (tid < 32) {
        unsigned int remv = 0u;
        for (int c = 0; c < nw; c++) {
            unsigned int alive = ~__shfl_sync(0xFFFFFFFFu, remv, c);
            if (c == nw - 1 && (n & 31)) alive &= (1u << (n & 31)) - 1u;
            while (alive) {
                int b = __ffs(alive) - 1;
                int i = (c << 5) + b;
                unsigned int row = (tid < nw) ? mask[i * MSTRIDE + tid] : 0u;
                remv |= row;
                unsigned int rowc = __shfl_sync(0xFFFFFFFFu, row, c);
                alive &= ~rowc;
                alive &= ~(1u << b);
            }
        }
        s_remv[tid] = remv;
    }
    __syncthreads();

    for (int j = tid; j < n; j += blockDim.x)
        out[spos[j] * 6 + 5] = ((s_remv[j >> 5] >> (j & 31)) & 1u) ? 0.0f : 1.0f;
}

// ---------------- launch ----------------
extern "C" void kernel_launch(void* const* d_in, const int* in_sizes, int n_in,
                              void* d_out, int out_size) {
    const float* probs   = (const float*)d_in[0];
    const float* deltas  = (const float*)d_in[1];
    const float* anchors = (const float*)d_in[2];
    float* out = (float*)d_out;

    int n_prop    = in_sizes[0] / 3;
    int n_anchors = in_sizes[2] / 4;
    int n_groups  = n_prop / 4;          // 4 props (12 floats = 3 float4) per thread-step

    const int nms_smem = NMS_CAP * (5 * 4 + 4 + MSTRIDE * 4);   // 156672 bytes
    static int attr_set = 0;
    if (!attr_set) {
        cudaFuncSetAttribute(k_nms, cudaFuncAttributeMaxDynamicSharedMemorySize, nms_smem);
        attr_set = 1;
    }

    int gb1 = (n_groups + 511) / 512;    // 1 group per thread
    int gb2 = (n_groups + 255) / 256;

    k_hist<<<gb1, 512>>>(probs, n_groups);
    k_binit<<<1, 1024>>>();
    k_hist2s<<<gb2, 256>>>(probs, n_groups);
    k_rank<<<128, 512>>>(deltas, anchors, out, n_anchors);
    k_nms<<<NGROUPS, 1024, nms_smem>>>(out);
}

// round 12
// speedup vs baseline: 1.2355x; 1.2355x over previous
#include <cuda_runtime.h>
#include <math.h>

#define K_TOP    6000
#define CAND_CAP 16384
#define BIN_CAP  16384
#define NMS_CAP  1024
#define HBINS    4096      // 12-bit histogram (top 12 bits of transformed score)
#define H2BINS   4096      // 12-bit refine histogram (bits [8,20))
#define MSTRIDE  33        // padded mask row stride (no 32-way bank conflicts)
#define NGROUPS  16
#define RTILE    1024      // ulonglong2 pairs per rank smem tile

// ---------------- scratch (device globals; no allocations) ----------------
__device__ unsigned int       g_hist[HBINS];
__device__ unsigned int       g_hist2[H2BINS];
__device__ unsigned int       g_meta[8];     // [3]=candidate counter [4]=bin counter
__device__ unsigned long long g_cand[CAND_CAP];
__device__ unsigned long long g_bin[BIN_CAP];
__device__ float4             g_gbox[NGROUPS * NMS_CAP];
__device__ int                g_gpos[NGROUPS * NMS_CAP];
__device__ unsigned int       g_gcnt[NGROUPS];

// order-preserving float<->uint transform
__device__ __forceinline__ unsigned int f2u(float f) {
    unsigned int b = __float_as_uint(f);
    return b ^ ((b & 0x80000000u) ? 0xFFFFFFFFu : 0x80000000u);
}
__device__ __forceinline__ float u2f(unsigned int u) {
    unsigned int b = (u & 0x80000000u) ? (u ^ 0x80000000u) : ~u;
    return __uint_as_float(b);
}

// warp-ballot-aggregated append of `key` when `e` is true
__device__ __forceinline__ void ballot_append(bool e, unsigned long long key,
                                              unsigned long long* buf,
                                              unsigned int* ctr,
                                              int lane, unsigned int cap) {
    unsigned int act = __activemask();
    unsigned int ball = __ballot_sync(act, e);
    if (!ball) return;
    int leader = __ffs(ball) - 1;
    unsigned int posb = 0;
    if (lane == leader) posb = atomicAdd(ctr, (unsigned int)__popc(ball));
    posb = __shfl_sync(act, posb, leader);
    if (e) {
        unsigned int my = posb + __popc(ball & ((1u << lane) - 1u));
        if (my < cap) buf[my] = key;
    }
}

// block-wide suffix-sum threshold find over histogram H[BINS]
template<int BINS, int NT>
__device__ __forceinline__ void find_threshold(const unsigned int* H,
                                               unsigned int need,
                                               unsigned int* ssum,
                                               volatile unsigned int* o_t,
                                               volatile unsigned int* o_cnt) {
    int tid = threadIdx.x;
    const int bpt = BINS / NT;
    unsigned int cs = 0;
    int base = tid * bpt;
#pragma unroll
    for (int k = 0; k < bpt; k++) cs += H[base + k];
    ssum[tid] = cs; __syncthreads();
    for (int off = 1; off < NT; off <<= 1) {           // inclusive suffix sum
        unsigned int v = (tid + off < NT) ? ssum[tid + off] : 0u;
        __syncthreads();
        ssum[tid] += v;
        __syncthreads();
    }
    unsigned int excl = (tid < NT - 1) ? ssum[tid + 1] : 0u;
    if (ssum[tid] >= need && excl < need) {            // unique crossing chunk
        unsigned int run = excl;
        for (int k = bpt - 1; k >= 0; k--) {
            unsigned int h = H[base + k];
            if (run + h >= need) { *o_t = (unsigned int)(base + k); *o_cnt = run; break; }
            run += h;
        }
    }
    __syncthreads();
}

// ---------------- kernel 1: 12-bit histogram of fg scores ----------------
__global__ void k_hist(const float* __restrict__ probs, int n_groups) {
    __shared__ unsigned int sh[HBINS];
    for (int k = threadIdx.x; k < HBINS; k += blockDim.x) sh[k] = 0u;
    __syncthreads();

    const float4* __restrict__ p4 = (const float4*)probs;
    int stride = gridDim.x * blockDim.x;
    for (int g = blockIdx.x * blockDim.x + threadIdx.x; g < n_groups; g += stride) {
        float4 A = p4[g * 3 + 0], B = p4[g * 3 + 1], C = p4[g * 3 + 2];
        float s[8] = {A.y, A.z, B.x, B.y, B.w, C.x, C.z, C.w};
#pragma unroll
        for (int k = 0; k < 8; k++) {
            unsigned int bin = f2u(s[k]) >> 20;
            unsigned int act = __activemask();
            unsigned int peers = __match_any_sync(act, bin);
            int leader = __ffs(peers) - 1;
            if ((threadIdx.x & 31) == leader)
                atomicAdd(&sh[bin], (unsigned int)__popc(peers));
        }
    }
    __syncthreads();
    for (int k = threadIdx.x; k < HBINS; k += blockDim.x) {
        unsigned int v = sh[k];
        if (v) atomicAdd(&g_hist[k], v);
    }
}

// --- kernel 2: fused refine-histogram + definite collect + bin stash ---
__global__ void k_hist2c(const float* __restrict__ probs, int n_groups) {
    __shared__ unsigned int sh[H2BINS];
    __shared__ unsigned int ssum[256];
    __shared__ unsigned int s_t, s_cnt;

    find_threshold<HBINS, 256>(g_hist, (unsigned)K_TOP, ssum, &s_t, &s_cnt);
    unsigned int t = s_t;

    for (int k = threadIdx.x; k < H2BINS; k += blockDim.x) sh[k] = 0u;
    __syncthreads();

    int lane = threadIdx.x & 31;
    const float4* __restrict__ p4 = (const float4*)probs;
    int stride = gridDim.x * blockDim.x;
    for (int g = blockIdx.x * blockDim.x + threadIdx.x; g < n_groups; g += stride) {
        float4 A = p4[g * 3 + 0], B = p4[g * 3 + 1], C = p4[g * 3 + 2];
        float s[8] = {A.y, A.z, B.x, B.y, B.w, C.x, C.z, C.w};
#pragma unroll
        for (int k = 0; k < 8; k++) {
            unsigned int u = f2u(s[k]);
            unsigned int hi = u >> 20;
            unsigned int flat = (unsigned int)((g * 4 + (k >> 1)) * 2 + (k & 1));
            unsigned long long key = ((unsigned long long)u << 32) |
                                     (unsigned long long)(0xFFFFFFFFu - flat);
            ballot_append(hi > t, key, g_cand, &g_meta[3], lane, CAND_CAP);
            bool inbin = (hi == t);
            ballot_append(inbin, key, g_bin, &g_meta[4], lane, BIN_CAP);
            if (inbin) atomicAdd(&sh[(u >> 8) & 0xFFFu], 1u);
        }
    }
    __syncthreads();
    for (int k = threadIdx.x; k < H2BINS; k += blockDim.x) {
        unsigned int v = sh[k];
        if (v) atomicAdd(&g_hist2[k], v);
    }
}

// --- kernel 3: filter bin keys by the refined 24-bit threshold, append ---
__global__ void k_filter() {
    __shared__ unsigned int ssum[256];
    __shared__ unsigned int s_t, s_cnt, s_t2, s_dum;
    int lane = threadIdx.x & 31;

    find_threshold<HBINS, 256>(g_hist, (unsigned)K_TOP, ssum, &s_t, &s_cnt);
    unsigned int need2 = (unsigned)K_TOP - s_cnt;
    find_threshold<H2BINS, 256>(g_hist2, need2, ssum, &s_t2, &s_dum);
    unsigned int t2 = s_t2;

    int nb = (int)min(g_meta[4], (unsigned int)BIN_CAP);
    int stride = gridDim.x * blockDim.x;
    for (int i = blockIdx.x * blockDim.x + threadIdx.x; i < nb; i += stride) {
        unsigned long long key = g_bin[i];
        unsigned int u = (unsigned int)(key >> 32);
        bool e = ((u >> 8) & 0xFFFu) >= t2;    // prefix == t12 for all bin keys
        ballot_append(e, key, g_cand, &g_meta[3], lane, CAND_CAP);
    }
}

// --- kernel 4: exact global rank via smem-tiled compare-count + decode ---
// 4 candidates per warp, 16 warps/block, 128 blocks (covers 8192 >= m).
__global__ __launch_bounds__(512, 2)
void k_rank(const float* __restrict__ deltas,
            const float* __restrict__ anchors,
            float* __restrict__ out, int n_anchors) {
    __shared__ ulonglong2 tile[RTILE];      // 16KB
    int m = (int)min(g_meta[3], (unsigned int)CAND_CAP);
    int lane = threadIdx.x & 31;
    int wid  = threadIdx.x >> 5;
    int c0 = (blockIdx.x * 16 + wid) * 4;

    unsigned long long ck[4];
    unsigned int cnt[4];
#pragma unroll
    for (int r = 0; r < 4; r++) {
        ck[r] = (c0 + r < m) ? g_cand[c0 + r] : 0xFFFFFFFFFFFFFFFFULL;
        cnt[r] = 0u;
    }

    const ulonglong2* __restrict__ p2 = (const ulonglong2*)g_cand;
    int mp = (m + 1) >> 1;                  // pairs; pad slot m is provably 0
    for (int t0 = 0; t0 < mp; t0 += RTILE) {
        int nt = min(RTILE, mp - t0);
        for (int i = threadIdx.x; i < nt; i += 512) tile[i] = p2[t0 + i];
        __syncthreads();
        int j = lane;
        for (; j + 32 < nt; j += 64) {      // 2-deep unroll: 4 keys / iter
            ulonglong2 a = tile[j], b = tile[j + 32];
#pragma unroll
            for (int r = 0; r < 4; r++) {
                cnt[r] += (a.x > ck[r]) ? 1u : 0u;
                cnt[r] += (a.y > ck[r]) ? 1u : 0u;
                cnt[r] += (b.x > ck[r]) ? 1u : 0u;
                cnt[r] += (b.y > ck[r]) ? 1u : 0u;
            }
        }
        for (; j < nt; j += 32) {
            ulonglong2 a = tile[j];
#pragma unroll
            for (int r = 0; r < 4; r++) {
                cnt[r] += (a.x > ck[r]) ? 1u : 0u;
                cnt[r] += (a.y > ck[r]) ? 1u : 0u;
            }
        }
        __syncthreads();
    }
#pragma unroll
    for (int r = 0; r < 4; r++) {
#pragma unroll
        for (int off = 16; off > 0; off >>= 1)
            cnt[r] += __shfl_down_sync(0xFFFFFFFFu, cnt[r], off);
    }

    if (lane == 0 && c0 < m) {
#pragma unroll
        for (int which = 0; which < 4; which++) {
            int c = c0 + which;
            if (c >= m) break;
            unsigned int cw = cnt[which];
            if (cw >= (unsigned)K_TOP) continue;
            unsigned long long ckey = ck[which];

            int rk = (int)cw;
            unsigned int u = (unsigned int)(ckey >> 32);
            unsigned int flat = 0xFFFFFFFFu - (unsigned int)(ckey & 0xFFFFFFFFu);
            int prop = (int)(flat >> 1);
            int cls = (int)(flat & 1u) + 1;
            float score = u2f(u);
            int b = prop / n_anchors;
            int ai = prop - b * n_anchors;

            const float* a  = anchors + (size_t)ai * 4;
            const float* dl = deltas + (size_t)prop * 4;
            float d0 = dl[0] * 0.1f, d1 = dl[1] * 0.1f;
            float d2 = dl[2] * 0.2f, d3 = dl[3] * 0.2f;

            const float inv = 1.0f / 512.0f;
            float ay1 = a[0] * inv, ax1 = a[1] * inv;
            float ay2 = a[2] * inv, ax2 = a[3] * inv;
            float h  = ay2 - ay1;
            float w2 = ax2 - ax1;
            float cy = ay1 + 0.5f * h + d0 * h;
            float cx = ax1 + 0.5f * w2 + d1 * w2;
            h  = h * expf(d2);
            w2 = w2 * expf(d3);
            float y1 = cy - 0.5f * h;
            float x1 = cx - 0.5f * w2;
            float y2 = y1 + h;
            float x2 = x1 + w2;
            y1 = fminf(fmaxf(y1 * 512.0f, 0.0f), 512.0f);
            x1 = fminf(fmaxf(x1 * 512.0f, 0.0f), 512.0f);
            y2 = fminf(fmaxf(y2 * 512.0f, 0.0f), 512.0f);
            x2 = fminf(fmaxf(x2 * 512.0f, 0.0f), 512.0f);

            out[rk * 6 + 0] = y1;
            out[rk * 6 + 1] = x1;
            out[rk * 6 + 2] = y2;
            out[rk * 6 + 3] = x2;
            out[rk * 6 + 4] = score;
            out[rk * 6 + 5] = 1.0f;                 // keep (finalized by NMS)
            out[K_TOP * 6 + rk] = (float)cls;       // class_ids
            out[K_TOP * 7 + rk] = (float)b;         // batch ids

            int grp = b * 2 + (int)(flat & 1u);
            unsigned int slot = atomicAdd(&g_gcnt[grp], 1u);   // arbitrary order
            if (slot < NMS_CAP) {
                g_gbox[grp * NMS_CAP + slot] = make_float4(y1, x1, y2, x2);
                g_gpos[grp * NMS_CAP + slot] = rk;
            }
        }
    }
}

// ------- kernel 5: per-group NMS (sorts by global rank first) + cleanup -------
__global__ void k_nms(float* __restrict__ out) {
    extern __shared__ unsigned char dyn[];
    float* sy1   = (float*)dyn;
    float* sx1   = sy1 + NMS_CAP;
    float* sy2   = sx1 + NMS_CAP;
    float* sx2   = sy2 + NMS_CAP;
    float* sarea = sx2 + NMS_CAP;
    int* spos    = (int*)(sarea + NMS_CAP);
    unsigned int* mask = (unsigned int*)(spos + NMS_CAP);   // [NMS_CAP][MSTRIDE]
    int* rkraw = (int*)mask;                                // pre-mask scratch

    __shared__ unsigned int s_remv[32];

    int tid = threadIdx.x;
    int grp = blockIdx.x;

    // cleanup scratch for next graph replay
    if (tid < HBINS / NGROUPS) g_hist[grp * (HBINS / NGROUPS) + tid] = 0u;
    else if (tid >= 256 && tid < 256 + H2BINS / NGROUPS)
        g_hist2[grp * (H2BINS / NGROUPS) + (tid - 256)] = 0u;
    if (grp == 0 && tid == 512) g_meta[3] = 0u;
    if (grp == 0 && tid == 513) g_meta[4] = 0u;

    int n = min((int)g_gcnt[grp], NMS_CAP);

    // load raw (unordered) entries; sort by global rank via rank-by-count
    float4 bx = make_float4(0.f, 0.f, 0.f, 0.f);
    int ps = 0;
    if (tid < n) {
        bx = g_gbox[grp * NMS_CAP + tid];
        ps = g_gpos[grp * NMS_CAP + tid];
        rkraw[tid] = ps;
    }
    __syncthreads();
    if (tid == 0) g_gcnt[grp] = 0u;
    int myrank = 0;
    if (tid < n)
        for (int j = 0; j < n; j++) myrank += (rkraw[j] < ps) ? 1 : 0;
    __syncthreads();
    if (tid < n) {
        sy1[myrank] = bx.x; sx1[myrank] = bx.y;
        sy2[myrank] = bx.z; sx2[myrank] = bx.w;
        sarea[myrank] = (bx.z - bx.x + 1.0f) * (bx.w - bx.y + 1.0f);
        spos[myrank] = ps;
    }
    __syncthreads();

    int nw = (n + 31) >> 5;

    // forward suppression masks; t = w*n + i (i fastest): lanes share w,
    // consecutive i -> conflict-free mask stores with MSTRIDE=33
    int total = nw * n;
    for (int t = tid; t < total; t += blockDim.x) {
        int w = t / n;
        int i = t - w * n;
        if (w < (i >> 5)) { mask[i * MSTRIDE + w] = 0u; continue; }
        float iy1 = sy1[i], ix1 = sx1[i], iy2 = sy2[i], ix2 = sx2[i];
        float ia = sarea[i];
        unsigned int mw = 0u;
        int jb = w << 5;
#pragma unroll 8
        for (int b = 0; b < 32; b++) {
            int j = jb + b;
            if (j > i && j < n) {
                float ih  = fminf(iy2, sy2[j]) - fmaxf(iy1, sy1[j]) + 1.0f;
                float iw2 = fminf(ix2, sx2[j]) - fmaxf(ix1, sx1[j]) + 1.0f;
                ih = fmaxf(ih, 0.0f); iw2 = fmaxf(iw2, 0.0f);
                float inter = ih * iw2;
                if (inter >= 0.5f * (ia + sarea[j] - inter)) mw |= (1u << b);
            }
        }
        mask[i * MSTRIDE + w] = mw;
    }
    __syncthreads();

    // greedy bit-reduce (warp 0), visiting only still-alive boxes via ffs
    if (tid < 32) {
        unsigned int remv = 0u;
        for (int c = 0; c < nw; c++) {
            unsigned int alive = ~__shfl_sync(0xFFFFFFFFu, remv, c);
            if (c == nw - 1 && (n & 31)) alive &= (1u << (n & 31)) - 1u;
            while (alive) {
                int b = __ffs(alive) - 1;
                int i = (c << 5) + b;
                unsigned int row = (tid < nw) ? mask[i * MSTRIDE + tid] : 0u;
                remv |= row;
                unsigned int rowc = __shfl_sync(0xFFFFFFFFu, row, c);
                alive &= ~rowc;
                alive &= ~(1u << b);
            }
        }
        s_remv[tid] = remv;
    }
    __syncthreads();

    for (int j = tid; j < n; j += blockDim.x)
        out[spos[j] * 6 + 5] = ((s_remv[j >> 5] >> (j & 31)) & 1u) ? 0.0f : 1.0f;
}

// ---------------- launch ----------------
extern "C" void kernel_launch(void* const* d_in, const int* in_sizes, int n_in,
                              void* d_out, int out_size) {
    const float* probs   = (const float*)d_in[0];
    const float* deltas  = (const float*)d_in[1];
    const float* anchors = (const float*)d_in[2];
    float* out = (float*)d_out;

    int n_prop    = in_sizes[0] / 3;
    int n_anchors = in_sizes[2] / 4;
    int n_groups  = n_prop / 4;          // 4 props (12 floats = 3 float4) per thread-step

    const int nms_smem = NMS_CAP * (5 * 4 + 4 + MSTRIDE * 4);   // 156672 bytes
    static int attr_set = 0;
    if (!attr_set) {
        cudaFuncSetAttribute(k_nms, cudaFuncAttributeMaxDynamicSharedMemorySize, nms_smem);
        attr_set = 1;
    }

    int gb1 = (n_groups + 511) / 512;    // 1 group per thread
    int gb2 = (n_groups + 255) / 256;

    k_hist<<<gb1, 512>>>(probs, n_groups);
    k_hist2c<<<gb2, 256>>>(probs, n_groups);
    k_filter<<<16, 256>>>();
    k_rank<<<128, 512>>>(deltas, anchors, out, n_anchors);
    k_nms<<<NGROUPS, 1024, nms_smem>>>(out);
}